// round 5
// baseline (speedup 1.0000x reference)
#include <cuda_runtime.h>
#include <stdint.h>

#define NW      12
#define DIM     4096
#define THREADS 512

typedef unsigned long long u64;

// ---------------------------------------------------------------------------
// Host-side GF(2) machinery.
// CNOT chain acts as index relabel p -> M p. We store amplitudes in the
// q = M p basis, where every layer-1 gate is a standard bit-stride gate:
// wire w pairs along bit (11-w) of q, branch = that bit.
// Measurement sign masks become rows of M (since M^2 M^-1 = M).
// ---------------------------------------------------------------------------

struct CircuitMasks {
    int minv_col[12];   // bit-space columns of M^-1 (for init: p = Minv q)
    int mrow[12];       // bit-space rows of M (for measurement weights)
};

static inline int wire2bits(unsigned wiremask) {
    int m = 0;
    for (int v = 0; v < NW; v++)
        if ((wiremask >> v) & 1) m |= 1 << (11 - v);
    return m;
}

static void compute_masks(CircuitMasks* cm) {
    unsigned M[NW];
    for (int w = 0; w < NW; w++) M[w] = 1u << w;
    for (int w = 0; w < NW - 1; w++) M[w + 1] ^= M[w];
    M[0] ^= M[NW - 1];

    unsigned A[NW], Inv[NW];
    for (int i = 0; i < NW; i++) { A[i] = M[i]; Inv[i] = 1u << i; }
    for (int col = 0; col < NW; col++) {
        int piv = -1;
        for (int r = col; r < NW; r++)
            if ((A[r] >> col) & 1) { piv = r; break; }
        unsigned ta = A[col]; A[col] = A[piv]; A[piv] = ta;
        unsigned ti = Inv[col]; Inv[col] = Inv[piv]; Inv[piv] = ti;
        for (int r = 0; r < NW; r++)
            if (r != col && ((A[r] >> col) & 1)) { A[r] ^= A[col]; Inv[r] ^= Inv[col]; }
    }
    unsigned colw[NW];
    for (int w = 0; w < NW; w++) {
        unsigned c = 0;
        for (int v = 0; v < NW; v++)
            if ((Inv[v] >> w) & 1) c |= 1u << v;
        colw[w] = c;
    }

    for (int j = 0; j < NW; j++) cm->minv_col[j] = wire2bits(colw[11 - j]);
    for (int w = 0; w < NW; w++) cm->mrow[w] = wire2bits(M[w]);
}

// ---------------------------------------------------------------------------
// Device
// ---------------------------------------------------------------------------

__device__ float g_weight[DIM];

__global__ void weight_kernel(const float* __restrict__ head_w, CircuitMasks cm) {
    int q = blockIdx.x * blockDim.x + threadIdx.x;
    if (q >= DIM) return;
    float acc = 0.f;
#pragma unroll
    for (int w = 0; w < NW; w++) {
        int par = __popc(q & cm.mrow[w]) & 1;
        acc += par ? -head_w[w] : head_w[w];
    }
    g_weight[q] = acc;
}

// packed f32x2 helpers (Blackwell FFMA2 path)
__device__ __forceinline__ u64 pack2(float a, float b) {
    u64 r; asm("mov.b64 %0, {%1, %2};" : "=l"(r) : "f"(a), "f"(b)); return r;
}
__device__ __forceinline__ u64 ffma2(u64 a, u64 b, u64 c) {
    u64 d; asm("fma.rn.f32x2 %0, %1, %2, %3;" : "=l"(d) : "l"(a), "l"(b), "l"(c)); return d;
}
__device__ __forceinline__ u64 fmul2(u64 a, u64 b) {
    u64 d; asm("mul.rn.f32x2 %0, %1, %2;" : "=l"(d) : "l"(a), "l"(b)); return d;
}
__device__ __forceinline__ float2 u2f(u64 a) {
    float2 f; asm("mov.b64 {%0, %1}, %2;" : "=f"(f.x), "=f"(f.y) : "l"(a)); return f;
}

// bank swizzle: phys(q) = q ^ ((q>>3)&15). Conflict-free (verified per
// 16-lane half) for all four phase access patterns below.
__device__ __forceinline__ int sw(int q) { return q ^ ((q >> 3) & 15); }

__global__ __launch_bounds__(THREADS, 4) void qsim_kernel(
    const float* __restrict__ state_batch,
    const float* __restrict__ params,
    const float* __restrict__ head_b,
    float* __restrict__ out,
    CircuitMasks cm) {
    __shared__ u64    s[DIM];
    __shared__ float2 f0[NW], f1[NW];     // per-wire product-state factors
    __shared__ float2 clo[64], chi[64];   // complex product tables (physical p space)
    __shared__ float2 gcs[NW];            // layer-1 RY (cos, sin) per wire
    __shared__ int    pr[8];              // Minv applied to low-3-bit nibbles
    __shared__ float  red[16];

    const int tid = threadIdx.x;
    const int b = blockIdx.x;

    // --- per-wire angles: RZ(phi) RY(theta + angle) |0>, layer-1 RY half angle
    if (tid < NW) {
        int w = tid;
        float ang = state_batch[(size_t)b * DIM + w];
        float th = 0.5f * (ang + params[w * 2 + 0]);     // params[0][w][0]
        float ph = 0.5f * params[w * 2 + 1];             // params[0][w][1]
        float sh, ch_, sp, cp;
        __sincosf(th, &sh, &ch_);
        __sincosf(ph, &sp, &cp);
        f0[w] = make_float2(cp * ch_, -sp * ch_);
        f1[w] = make_float2(cp * sh, sp * sh);
        float t2 = 0.5f * params[2 * NW + w * 2 + 0];    // params[1][w][0]
        float s2, c2;
        __sincosf(t2, &s2, &c2);
        gcs[w] = make_float2(c2, s2);
        // (layer-1 RZ dropped: diagonal before a basis permutation + |.|^2)
    }
    if (tid < 8) {
        int r = tid, p = 0;
        if (r & 1) p ^= cm.minv_col[0];
        if (r & 2) p ^= cm.minv_col[1];
        if (r & 4) p ^= cm.minv_col[2];
        pr[r] = p;
    }
    __syncthreads();

    // --- product tables in physical space: bit j of p <-> wire (11-j)
    if (tid < 128) {
        int m = tid & 63;
        bool hi = tid >= 64;
        float2 acc = make_float2(1.f, 0.f);
#pragma unroll
        for (int j = 0; j < 6; j++) {
            int bit = (m >> j) & 1;
            int w = hi ? (5 - j) : (11 - j);
            float2 f = bit ? f1[w] : f0[w];
            acc = make_float2(acc.x * f.x - acc.y * f.y,
                              acc.x * f.y + acc.y * f.x);
        }
        if (hi) chi[m] = acc; else clo[m] = acc;
    }
    __syncthreads();

    // --- init 8 amplitudes into registers (phase A: q = (tid<<3)|r)
    int pb = 0;
#pragma unroll
    for (int i = 0; i < 9; i++)
        if ((tid >> i) & 1) pb ^= cm.minv_col[i + 3];

    u64 v[8];
#pragma unroll
    for (int r = 0; r < 8; r++) {
        int p = pb ^ pr[r];
        float2 lo = clo[p & 63], hi = chi[p >> 6];
        v[r] = pack2(fmaf(hi.x, lo.x, -hi.y * lo.y),
                     fmaf(hi.x, lo.y,  hi.y * lo.x));
    }

    // gate on register bit bp (0..2) with angle of 'wire' (packed f32x2 math)
#define APPLY_BIT(bp, wire) {                                           \
        float c_ = gcs[wire].x, sn_ = gcs[wire].y;                      \
        u64 c2_ = pack2(c_, c_), s2_ = pack2(sn_, sn_);                 \
        u64 ns2_ = pack2(-sn_, -sn_);                                   \
        _Pragma("unroll")                                               \
        for (int r = 0; r < 8; r++) if (!(r & (1 << bp))) {             \
            int r1 = r | (1 << bp);                                     \
            u64 a_ = v[r], d_ = v[r1];                                  \
            v[r]  = ffma2(c2_, a_, fmul2(ns2_, d_));                    \
            v[r1] = ffma2(s2_, a_, fmul2(c2_,  d_));                    \
        }                                                               \
    }

    // --- phase A: regs = q bits 0..2 -> wires 11,10,9
    APPLY_BIT(0, 11); APPLY_BIT(1, 10); APPLY_BIT(2, 9);
#pragma unroll
    for (int r = 0; r < 8; r++)
        s[sw((tid << 3) | r)] = v[r];
    __syncthreads();

    // --- phase B: regs = q bits 3..5 -> wires 8,7,6
    // q = ((tid>>3)<<6) | (r<<3) | (tid&7)
    {
        const int baseB = ((tid >> 3) << 6) | (tid & 7);
#pragma unroll
        for (int r = 0; r < 8; r++)
            v[r] = s[sw(baseB | (r << 3))];
        APPLY_BIT(0, 8); APPLY_BIT(1, 7); APPLY_BIT(2, 6);
#pragma unroll
        for (int r = 0; r < 8; r++)
            s[sw(baseB | (r << 3))] = v[r];
    }
    __syncthreads();

    // --- phase C: regs = q bits 6..8 -> wires 5,4,3
    // q = ((tid>>6)<<9) | (r<<6) | (tid&63)
    {
        const int baseC = ((tid >> 6) << 9) | (tid & 63);
#pragma unroll
        for (int r = 0; r < 8; r++)
            v[r] = s[sw(baseC | (r << 6))];
        APPLY_BIT(0, 5); APPLY_BIT(1, 4); APPLY_BIT(2, 3);
#pragma unroll
        for (int r = 0; r < 8; r++)
            s[sw(baseC | (r << 6))] = v[r];
    }
    __syncthreads();

    // --- phase D: regs = q bits 9..11 -> wires 2,1,0; q = (r<<9) | tid
#pragma unroll
    for (int r = 0; r < 8; r++)
        v[r] = s[sw((r << 9) | tid)];
    APPLY_BIT(0, 2); APPLY_BIT(1, 1); APPLY_BIT(2, 0);

    // --- measurement: weight table indexed in q space (rows of M folded in)
    float acc = 0.f;
#pragma unroll
    for (int r = 0; r < 8; r++) {
        float2 a = u2f(v[r]);
        acc = fmaf(fmaf(a.x, a.x, a.y * a.y), g_weight[(r << 9) | tid], acc);
    }
#pragma unroll
    for (int o = 16; o > 0; o >>= 1)
        acc += __shfl_xor_sync(0xffffffffu, acc, o);
    if ((tid & 31) == 0) red[tid >> 5] = acc;
    __syncthreads();
    if (tid == 0) {
        float t = 0.f;
#pragma unroll
        for (int i = 0; i < 16; i++) t += red[i];
        out[b] = t + head_b[0];
    }
#undef APPLY_BIT
}

// ---------------------------------------------------------------------------

extern "C" void kernel_launch(void* const* d_in, const int* in_sizes, int n_in,
                              void* d_out, int out_size) {
    const float* state_batch = (const float*)d_in[0];
    const float* params      = (const float*)d_in[1];
    const float* head_w      = (const float*)d_in[2];
    const float* head_b      = (const float*)d_in[3];
    float* out = (float*)d_out;

    CircuitMasks cm;
    compute_masks(&cm);

    weight_kernel<<<16, 256>>>(head_w, cm);
    qsim_kernel<<<out_size, THREADS>>>(state_batch, params, head_b, out, cm);
}

// round 6
// speedup vs baseline: 1.1631x; 1.1631x over previous
#include <cuda_runtime.h>
#include <stdint.h>

#define NW      12
#define DIM     4096
#define THREADS 256

typedef unsigned long long u64;

// ---------------------------------------------------------------------------
// Host-side GF(2) machinery.
// CNOT chain acts as index relabel p -> M p. We store amplitudes in the
// q = M p basis, where every layer-1 gate is a standard bit-stride gate:
// wire w pairs along bit (11-w) of q, branch = that bit.
// Measurement sign masks become rows of M (since M^2 M^-1 = M).
// Layer-1 RY gates use the tan factorization RY = cos(th) * [1,-t;t,1];
// the global prod(cos)^2 is folded into the measurement weight table.
// ---------------------------------------------------------------------------

struct CircuitMasks {
    int minv_col[12];   // bit-space columns of M^-1 (for init: p = Minv q)
    int mrow[12];       // bit-space rows of M (for measurement weights)
};

static inline int wire2bits(unsigned wiremask) {
    int m = 0;
    for (int v = 0; v < NW; v++)
        if ((wiremask >> v) & 1) m |= 1 << (11 - v);
    return m;
}

static void compute_masks(CircuitMasks* cm) {
    unsigned M[NW];
    for (int w = 0; w < NW; w++) M[w] = 1u << w;
    for (int w = 0; w < NW - 1; w++) M[w + 1] ^= M[w];
    M[0] ^= M[NW - 1];

    unsigned A[NW], Inv[NW];
    for (int i = 0; i < NW; i++) { A[i] = M[i]; Inv[i] = 1u << i; }
    for (int col = 0; col < NW; col++) {
        int piv = -1;
        for (int r = col; r < NW; r++)
            if ((A[r] >> col) & 1) { piv = r; break; }
        unsigned ta = A[col]; A[col] = A[piv]; A[piv] = ta;
        unsigned ti = Inv[col]; Inv[col] = Inv[piv]; Inv[piv] = ti;
        for (int r = 0; r < NW; r++)
            if (r != col && ((A[r] >> col) & 1)) { A[r] ^= A[col]; Inv[r] ^= Inv[col]; }
    }
    unsigned colw[NW];
    for (int w = 0; w < NW; w++) {
        unsigned c = 0;
        for (int v = 0; v < NW; v++)
            if ((Inv[v] >> w) & 1) c |= 1u << v;
        colw[w] = c;
    }

    for (int j = 0; j < NW; j++) cm->minv_col[j] = wire2bits(colw[11 - j]);
    for (int w = 0; w < NW; w++) cm->mrow[w] = wire2bits(M[w]);
}

// ---------------------------------------------------------------------------
// Device
// ---------------------------------------------------------------------------

__device__ float g_weight[DIM];

// weight = (sum_w sign_w(q) head_w) * prod_w cos^2(0.5*theta2_w)
__global__ void weight_kernel(const float* __restrict__ head_w,
                              const float* __restrict__ params,
                              CircuitMasks cm) {
    int q = blockIdx.x * blockDim.x + threadIdx.x;
    if (q >= DIM) return;
    float acc = 0.f;
#pragma unroll
    for (int w = 0; w < NW; w++) {
        int par = __popc(q & cm.mrow[w]) & 1;
        acc += par ? -head_w[w] : head_w[w];
    }
    float C = 1.f;
#pragma unroll
    for (int w = 0; w < NW; w++)
        C *= cosf(0.5f * params[2 * NW + w * 2 + 0]);   // params[1][w][0]
    g_weight[q] = acc * C * C;
}

// packed f32x2 helpers (Blackwell FFMA2 path)
__device__ __forceinline__ u64 pack2(float a, float b) {
    u64 r; asm("mov.b64 %0, {%1, %2};" : "=l"(r) : "f"(a), "f"(b)); return r;
}
__device__ __forceinline__ u64 ffma2(u64 a, u64 b, u64 c) {
    u64 d; asm("fma.rn.f32x2 %0, %1, %2, %3;" : "=l"(d) : "l"(a), "l"(b), "l"(c)); return d;
}
__device__ __forceinline__ float2 u2f(u64 a) {
    float2 f; asm("mov.b64 {%0, %1}, %2;" : "=f"(f.x), "=f"(f.y) : "l"(a)); return f;
}

__global__ __launch_bounds__(THREADS, 5) void qsim_kernel(
    const float* __restrict__ state_batch,
    const float* __restrict__ params,
    const float* __restrict__ head_b,
    float* __restrict__ out,
    CircuitMasks cm) {
    __shared__ u64    s[DIM];
    __shared__ float2 f0[NW], f1[NW];     // per-wire product-state factors
    __shared__ float2 clo[64], chi[64];   // complex product tables (physical p space)
    __shared__ float  gt[NW];             // layer-1 RY tan(theta) per wire
    __shared__ int    pr[16];             // Minv applied to low-4-bit nibbles
    __shared__ float  red[8];

    const int tid = threadIdx.x;
    const int b = blockIdx.x;

    // --- per-wire angles: RZ(phi) RY(theta + angle) |0>, layer-1 RY tan
    if (tid < NW) {
        int w = tid;
        float ang = state_batch[(size_t)b * DIM + w];
        float th = 0.5f * (ang + params[w * 2 + 0]);     // params[0][w][0]
        float ph = 0.5f * params[w * 2 + 1];             // params[0][w][1]
        float sh, ch_, sp, cp;
        __sincosf(th, &sh, &ch_);
        __sincosf(ph, &sp, &cp);
        f0[w] = make_float2(cp * ch_, -sp * ch_);
        f1[w] = make_float2(cp * sh, sp * sh);
        float t2 = 0.5f * params[2 * NW + w * 2 + 0];    // params[1][w][0]
        float s2, c2;
        __sincosf(t2, &s2, &c2);
        gt[w] = s2 / c2;                                 // tan; cos folded into weight
        // (layer-1 RZ dropped: diagonal before a basis permutation + |.|^2)
    }
    if (tid < 16) {
        int r = tid, p = 0;
        if (r & 1) p ^= cm.minv_col[0];
        if (r & 2) p ^= cm.minv_col[1];
        if (r & 4) p ^= cm.minv_col[2];
        if (r & 8) p ^= cm.minv_col[3];
        pr[r] = p;
    }
    __syncthreads();

    // --- product tables in physical space: bit j of p <-> wire (11-j)
    if (tid < 128) {
        int m = tid & 63;
        bool hi = tid >= 64;
        float2 acc = make_float2(1.f, 0.f);
#pragma unroll
        for (int j = 0; j < 6; j++) {
            int bit = (m >> j) & 1;
            int w = hi ? (5 - j) : (11 - j);
            float2 f = bit ? f1[w] : f0[w];
            acc = make_float2(acc.x * f.x - acc.y * f.y,
                              acc.x * f.y + acc.y * f.x);
        }
        if (hi) chi[m] = acc; else clo[m] = acc;
    }
    __syncthreads();

    // --- init 16 amplitudes straight into registers (mapping1: q = (tid<<4)|r)
    int pb = 0;
#pragma unroll
    for (int i = 0; i < 8; i++)
        if ((tid >> i) & 1) pb ^= cm.minv_col[i + 4];

    u64 v[16];
#pragma unroll
    for (int r = 0; r < 16; r++) {
        int p = pb ^ pr[r];
        float2 lo = clo[p & 63], hi = chi[p >> 6];
        v[r] = pack2(fmaf(hi.x, lo.x, -hi.y * lo.y),
                     fmaf(hi.x, lo.y,  hi.y * lo.x));
    }

    // tan-form gate on register bit bp: v0' = v0 - t v1 ; v1' = t v0 + v1
#define APPLY_BIT(bp, wire) {                                           \
        float t_ = gt[wire];                                            \
        u64 t2_ = pack2(t_, t_), nt2_ = pack2(-t_, -t_);                \
        _Pragma("unroll")                                               \
        for (int r = 0; r < 16; r++) if (!(r & (1 << bp))) {            \
            int r1 = r | (1 << bp);                                     \
            u64 a_ = v[r], d_ = v[r1];                                  \
            v[r]  = ffma2(nt2_, d_, a_);                                \
            v[r1] = ffma2(t2_,  a_, d_);                                \
        }                                                               \
    }

    // --- phase 1: q bits 0..3 in regs -> wires 11,10,9,8
    APPLY_BIT(0, 11); APPLY_BIT(1, 10); APPLY_BIT(2, 9); APPLY_BIT(3, 8);

    const int tx = tid & 15;

    // transpose 1: write mapping1 (phys = (t<<4) | (r^tx))
#pragma unroll
    for (int r = 0; r < 16; r++)
        s[(tid << 4) | (r ^ tx)] = v[r];
    __syncthreads();

    // --- phase 2: read mapping2 (regs = q bits 4..7)
    const int base2 = ((tid >> 4) << 8);
#pragma unroll
    for (int r = 0; r < 16; r++)
        v[r] = s[base2 | (r << 4) | (tx ^ r)];

    // wires 7,6,5,4
    APPLY_BIT(0, 7); APPLY_BIT(1, 6); APPLY_BIT(2, 5); APPLY_BIT(3, 4);

    // write back to the SAME slots this thread read -> no sync needed before
#pragma unroll
    for (int r = 0; r < 16; r++)
        s[base2 | (r << 4) | (tx ^ r)] = v[r];
    __syncthreads();

    // --- phase 3: read mapping3 (regs = q bits 8..11)
    const int thi = tid & 0xF0;
    const int swz3 = tx ^ (tid >> 4);
#pragma unroll
    for (int r = 0; r < 16; r++)
        v[r] = s[(r << 8) | thi | swz3];

    // wires 3,2,1,0
    APPLY_BIT(0, 3); APPLY_BIT(1, 2); APPLY_BIT(2, 1); APPLY_BIT(3, 0);

    // --- measurement: weight table (q space, rows of M + prod cos^2 folded in)
    float acc = 0.f;
#pragma unroll
    for (int r = 0; r < 16; r++) {
        float2 a = u2f(v[r]);
        acc = fmaf(fmaf(a.x, a.x, a.y * a.y), g_weight[(r << 8) | tid], acc);
    }
#pragma unroll
    for (int o = 16; o > 0; o >>= 1)
        acc += __shfl_xor_sync(0xffffffffu, acc, o);
    if ((tid & 31) == 0) red[tid >> 5] = acc;
    __syncthreads();
    if (tid == 0) {
        float t = 0.f;
#pragma unroll
        for (int i = 0; i < 8; i++) t += red[i];
        out[b] = t + head_b[0];
    }
#undef APPLY_BIT
}

// ---------------------------------------------------------------------------

extern "C" void kernel_launch(void* const* d_in, const int* in_sizes, int n_in,
                              void* d_out, int out_size) {
    const float* state_batch = (const float*)d_in[0];
    const float* params      = (const float*)d_in[1];
    const float* head_w      = (const float*)d_in[2];
    const float* head_b      = (const float*)d_in[3];
    float* out = (float*)d_out;

    CircuitMasks cm;
    compute_masks(&cm);

    weight_kernel<<<16, 256>>>(head_w, params, cm);
    qsim_kernel<<<out_size, THREADS>>>(state_batch, params, head_b, out, cm);
}